// round 7
// baseline (speedup 1.0000x reference)
#include <cuda_runtime.h>
#include <cuda_bf16.h>
#include <cstdint>

#define BB 4
#define CC 512
#define CQ 64
#define DD 128   // 2*CQ
#define NN 4096  // H*W

// ---------------- scratch (device globals; no allocations allowed) ----------
__device__ __align__(256) __nv_bfloat16 g_xt_hi[BB * NN * CC];  // x^T [b][n][c]
__device__ __align__(256) __nv_bfloat16 g_xt_lo[BB * NN * CC];
__device__ __align__(256) __nv_bfloat16 g_dt_hi[BB * NN * CC];  // dep^T
__device__ __align__(256) __nv_bfloat16 g_dt_lo[BB * NN * CC];
__device__ __align__(256) __nv_bfloat16 g_wqk_hi[DD * CC];      // wq rows 0-63, wk rows 64-127
__device__ __align__(256) __nv_bfloat16 g_wqk_lo[DD * CC];
__device__ __align__(256) __nv_bfloat16 g_wqkd_hi[DD * CC];
__device__ __align__(256) __nv_bfloat16 g_wqkd_lo[DD * CC];
__device__ __align__(256) __nv_bfloat16 g_wv_hi[CC * CC];
__device__ __align__(256) __nv_bfloat16 g_wv_lo[CC * CC];
__device__ __align__(256) __nv_bfloat16 g_qhi[BB * NN * DD];    // [b][i][d]
__device__ __align__(256) __nv_bfloat16 g_qlo[BB * NN * DD];
__device__ __align__(256) __nv_bfloat16 g_khi[BB * NN * DD];
__device__ __align__(256) __nv_bfloat16 g_klo[BB * NN * DD];
__device__ __align__(256) __nv_bfloat16 g_vhi[BB * CC * NN];    // [b][c][n]
__device__ __align__(256) __nv_bfloat16 g_vlo[BB * CC * NN];
__device__ __align__(256) float g_e[(size_t)BB * NN * NN];
__device__ __align__(256) __nv_bfloat16 g_phi[(size_t)BB * NN * NN];
__device__ __align__(256) __nv_bfloat16 g_plo[(size_t)BB * NN * NN];
__device__ __align__(256) float g_s[BB * NN];

// ---------------- low-level helpers -----------------------------------------
__device__ __forceinline__ uint32_t smem_to_u32(const void* p) {
    uint32_t a;
    asm("{ .reg .u64 t; cvta.to.shared.u64 t, %1; cvt.u32.u64 %0, t; }" : "=r"(a) : "l"(p));
    return a;
}
#define SWZ(off) ((off) ^ (((off) >> 3) & 0x70))

__device__ __forceinline__ void cp16(uint32_t dst, const void* src) {
    asm volatile("cp.async.cg.shared.global [%0], [%1], 16;" :: "r"(dst), "l"(src));
}
__device__ __forceinline__ void cp_commit() {
    asm volatile("cp.async.commit_group;" ::: "memory");
}
__device__ __forceinline__ void ldsm4(uint32_t r[4], uint32_t addr) {
    asm volatile("ldmatrix.sync.aligned.m8n8.x4.shared.b16 {%0,%1,%2,%3}, [%4];"
                 : "=r"(r[0]), "=r"(r[1]), "=r"(r[2]), "=r"(r[3]) : "r"(addr));
}
__device__ __forceinline__ void mma_bf16(float acc[4], const uint32_t a[4],
                                         uint32_t b0, uint32_t b1) {
    asm volatile("mma.sync.aligned.m16n8k16.row.col.f32.bf16.bf16.f32 "
                 "{%0,%1,%2,%3}, {%4,%5,%6,%7}, {%8,%9}, {%0,%1,%2,%3};"
                 : "+f"(acc[0]), "+f"(acc[1]), "+f"(acc[2]), "+f"(acc[3])
                 : "r"(a[0]), "r"(a[1]), "r"(a[2]), "r"(a[3]), "r"(b0), "r"(b1));
}
__device__ __forceinline__ void split4(const float f[4], __nv_bfloat16 h[4], __nv_bfloat16 l[4])
{
#pragma unroll
    for (int i = 0; i < 4; i++) {
        h[i] = __float2bfloat16(f[i]);
        l[i] = __float2bfloat16(f[i] - __bfloat162float(h[i]));
    }
}
__device__ __forceinline__ void split_store2(float v0, float v1,
                                             __nv_bfloat16* dh, __nv_bfloat16* dl)
{
    __nv_bfloat16 h0 = __float2bfloat16(v0), h1 = __float2bfloat16(v1);
    __nv_bfloat16 l0 = __float2bfloat16(v0 - __bfloat162float(h0));
    __nv_bfloat16 l1 = __float2bfloat16(v1 - __bfloat162float(h1));
    __nv_bfloat162 H; H.x = h0; H.y = h1;
    __nv_bfloat162 L; L.x = l0; L.y = l1;
    *(__nv_bfloat162*)dh = H;
    *(__nv_bfloat162*)dl = L;
}

// ---------------- split-bf16 MMA machinery ----------------------------------
// Stage layout (64KB/stage, 3 stages = 192KB):
//   +0      A_hi 128x64 bf16 (128B swizzled rows)
//   +16384  A_lo
//   +32768  B_hi
//   +49152  B_lo
#define STG 65536
#define MMA_SMEM_BYTES (3 * STG)

__device__ __forceinline__ void stage_load(
    const __nv_bfloat16* __restrict__ Ahi, const __nv_bfloat16* __restrict__ Alo,
    size_t aStr,
    const __nv_bfloat16* __restrict__ Bhi, const __nv_bfloat16* __restrict__ Blo,
    size_t bStr, int kt, uint32_t stageU32, int t)
{
#pragma unroll
    for (int i = 0; i < 4; i++) {
        const int id = t + i * 256;
        const int row = id >> 3, c16 = id & 7;
        const uint32_t doff = SWZ((uint32_t)(row * 128 + c16 * 16));
        const size_t so = (size_t)row * aStr + kt + c16 * 8;
        cp16(stageU32 + doff,          Ahi + so);
        cp16(stageU32 + 16384 + doff,  Alo + so);
        const size_t sb = (size_t)row * bStr + kt + c16 * 8;
        cp16(stageU32 + 32768 + doff,  Bhi + sb);
        cp16(stageU32 + 49152 + doff,  Blo + sb);
    }
}

__device__ __forceinline__ void stage_compute(uint32_t stageU32, int wid, int lane,
                                              float acc[4][4][4])
{
    const int warp_row = wid >> 2;
    const int warp_col = wid & 3;
    const int lrow = lane & 15;
    const int chalf = (lane >= 16) ? 16 : 0;

#pragma unroll
    for (int ks = 0; ks < 4; ks++) {
        const uint32_t bcol = ks * 32 + chalf;
        uint32_t ahi[4][4], alo[4][4];
#pragma unroll
        for (int mi = 0; mi < 4; mi++) {
            const uint32_t off = SWZ((uint32_t)((warp_row * 64 + mi * 16 + lrow) * 128 + bcol));
            ldsm4(ahi[mi], stageU32 + off);
            ldsm4(alo[mi], stageU32 + 16384 + off);
        }
        uint32_t bhi[2][4], blo[2][4];
#pragma unroll
        for (int nh = 0; nh < 2; nh++) {
            const uint32_t off = SWZ((uint32_t)((warp_col * 32 + nh * 16 + lrow) * 128 + bcol));
            ldsm4(bhi[nh], stageU32 + 32768 + off);
            ldsm4(blo[nh], stageU32 + 49152 + off);
        }
#pragma unroll
        for (int mi = 0; mi < 4; mi++)
#pragma unroll
            for (int ni = 0; ni < 4; ni++) {
                const int nh = ni >> 1, s = ni & 1;
                mma_bf16(acc[mi][ni], ahi[mi], bhi[nh][s], bhi[nh][s + 2]);
                mma_bf16(acc[mi][ni], alo[mi], bhi[nh][s], bhi[nh][s + 2]);
                mma_bf16(acc[mi][ni], ahi[mi], blo[nh][s], blo[nh][s + 2]);
            }
    }
}

// 3-stage pipelined K loop, single __syncthreads per chunk.
template <int KCHUNKS>
__device__ __forceinline__ void mma_mainloop(
    const __nv_bfloat16* Ahi, const __nv_bfloat16* Alo, size_t aStr,
    const __nv_bfloat16* Bhi, const __nv_bfloat16* Blo, size_t bStr,
    uint32_t smemU32, int t, int wid, int lane, float acc[4][4][4])
{
    stage_load(Ahi, Alo, aStr, Bhi, Blo, bStr, 0, smemU32, t);
    cp_commit();
    if (KCHUNKS > 1) {
        stage_load(Ahi, Alo, aStr, Bhi, Blo, bStr, 64, smemU32 + STG, t);
        cp_commit();
    }
#pragma unroll 1
    for (int c = 0; c < KCHUNKS; c++) {
        if (c < KCHUNKS - 1)
            asm volatile("cp.async.wait_group 1;" ::: "memory");
        else
            asm volatile("cp.async.wait_group 0;" ::: "memory");
        __syncthreads();
        if (c + 2 < KCHUNKS) {
            stage_load(Ahi, Alo, aStr, Bhi, Blo, bStr, (c + 2) * 64,
                       smemU32 + ((c + 2) % 3) * STG, t);
            cp_commit();
        }
        stage_compute(smemU32 + (c % 3) * STG, wid, lane, acc);
    }
}

// ============================================================================
// transpose + split: src [b][C][N] fp32 -> dst [b][N][C] bf16 hi/lo
// ============================================================================
__global__ void __launch_bounds__(256)
transpose_split(const float* __restrict__ src,
                __nv_bfloat16* __restrict__ dhi, __nv_bfloat16* __restrict__ dlo)
{
    __shared__ float tile[32][33];
    const int b = blockIdx.z;
    const int n0 = blockIdx.x * 32, c0 = blockIdx.y * 32;
    const int tx = threadIdx.x, ty = threadIdx.y;   // (32, 8)
    const float* S = src + (size_t)b * CC * NN;
#pragma unroll
    for (int i = 0; i < 4; i++)
        tile[ty * 4 + i][tx] = S[(size_t)(c0 + ty * 4 + i) * NN + n0 + tx];
    __syncthreads();
    __nv_bfloat16* H = dhi + (size_t)b * NN * CC;
    __nv_bfloat16* L = dlo + (size_t)b * NN * CC;
#pragma unroll
    for (int i = 0; i < 4; i++) {
        const float f = tile[tx][ty * 4 + i];
        const __nv_bfloat16 h = __float2bfloat16(f);
        const __nv_bfloat16 l = __float2bfloat16(f - __bfloat162float(h));
        const size_t idx = (size_t)(n0 + ty * 4 + i) * CC + c0 + tx;
        H[idx] = h;
        L[idx] = l;
    }
}

// ============================================================================
// weight split: wv (512 rows) + wq/wk -> wqk (128 rows) + wqd/wkd -> wqkd
// ============================================================================
__global__ void __launch_bounds__(256)
weight_split(const float* __restrict__ wq, const float* __restrict__ wk,
             const float* __restrict__ wqd, const float* __restrict__ wkd,
             const float* __restrict__ wv,
             __nv_bfloat16* __restrict__ wqk_hi, __nv_bfloat16* __restrict__ wqk_lo,
             __nv_bfloat16* __restrict__ wqkd_hi, __nv_bfloat16* __restrict__ wqkd_lo,
             __nv_bfloat16* __restrict__ wv_hi, __nv_bfloat16* __restrict__ wv_lo)
{
    const int idx = blockIdx.x * 256 + threadIdx.x;
    if (idx >= 768 * 512) return;
    const int row = idx >> 9, col = idx & 511;
    const float* src;
    __nv_bfloat16 *dh, *dl;
    int drow;
    if (row < 512)      { src = wv  + (size_t)row * 512;         dh = wv_hi;   dl = wv_lo;   drow = row; }
    else if (row < 576) { src = wq  + (size_t)(row - 512) * 512; dh = wqk_hi;  dl = wqk_lo;  drow = row - 512; }
    else if (row < 640) { src = wk  + (size_t)(row - 576) * 512; dh = wqk_hi;  dl = wqk_lo;  drow = row - 576 + 64; }
    else if (row < 704) { src = wqd + (size_t)(row - 640) * 512; dh = wqkd_hi; dl = wqkd_lo; drow = row - 640; }
    else                { src = wkd + (size_t)(row - 704) * 512; dh = wqkd_hi; dl = wqkd_lo; drow = row - 704 + 64; }
    const float f = src[col];
    const __nv_bfloat16 h = __float2bfloat16(f);
    dh[(size_t)drow * 512 + col] = h;
    dl[(size_t)drow * 512 + col] = __float2bfloat16(f - __bfloat162float(h));
}

// ============================================================================
// proj qk: [n][d] tile = xt[n][c] . wqk[d][c],  d 0-63 -> q(+d_off), 64-127 -> k
// ============================================================================
__global__ void __launch_bounds__(256, 1)
mma_proj_qk(const __nv_bfloat16* __restrict__ xt_hi, const __nv_bfloat16* __restrict__ xt_lo,
            const __nv_bfloat16* __restrict__ w_hi,  const __nv_bfloat16* __restrict__ w_lo,
            const float* __restrict__ bias_q, const float* __restrict__ bias_k,
            __nv_bfloat16* __restrict__ Qhi, __nv_bfloat16* __restrict__ Qlo,
            __nv_bfloat16* __restrict__ Khi, __nv_bfloat16* __restrict__ Klo,
            int d_off)
{
    extern __shared__ char smem[];
    const uint32_t smemU32 = smem_to_u32(smem);
    const int t = threadIdx.x, wid = t >> 5, lane = t & 31;
    const int b = blockIdx.z;
    const int i0 = blockIdx.x * 128;

    const size_t aoff = ((size_t)b * NN + i0) * CC;
    float acc[4][4][4] = {};
    mma_mainloop<8>(xt_hi + aoff, xt_lo + aoff, CC, w_hi, w_lo, CC,
                    smemU32, t, wid, lane, acc);

    const int warp_col = wid & 3;
    const bool isK = warp_col >= 2;
    const float* bias = isK ? bias_k : bias_q;
    __nv_bfloat16* DH = isK ? Khi : Qhi;
    __nv_bfloat16* DL = isK ? Klo : Qlo;
    const int csub = isK ? 64 : 0;

    const int rbase = i0 + (wid >> 2) * 64 + (lane >> 2);
    const int cbase = warp_col * 32 + (lane & 3) * 2;
#pragma unroll
    for (int mi = 0; mi < 4; mi++)
#pragma unroll
        for (int ni = 0; ni < 4; ni++) {
            const int col = cbase + ni * 8 - csub;   // 0..63
            const float2 bi = *(const float2*)&bias[col];
            const int r0 = rbase + mi * 16;
            const size_t a0 = ((size_t)b * NN + r0) * DD + d_off + col;
            split_store2(acc[mi][ni][0] + bi.x, acc[mi][ni][1] + bi.y, DH + a0, DL + a0);
            const size_t a1 = ((size_t)b * NN + r0 + 8) * DD + d_off + col;
            split_store2(acc[mi][ni][2] + bi.x, acc[mi][ni][3] + bi.y, DH + a1, DL + a1);
        }
}

// ============================================================================
// proj v: [c][n] tile = wv[c][k] . xt[n][k]
// ============================================================================
__global__ void __launch_bounds__(256, 1)
mma_proj_v(const __nv_bfloat16* __restrict__ w_hi, const __nv_bfloat16* __restrict__ w_lo,
           const __nv_bfloat16* __restrict__ xt_hi, const __nv_bfloat16* __restrict__ xt_lo,
           const float* __restrict__ bias,
           __nv_bfloat16* __restrict__ Vhi, __nv_bfloat16* __restrict__ Vlo)
{
    extern __shared__ char smem[];
    const uint32_t smemU32 = smem_to_u32(smem);
    const int t = threadIdx.x, wid = t >> 5, lane = t & 31;
    const int b = blockIdx.z;
    const int n0 = blockIdx.x * 128, m0 = blockIdx.y * 128;

    const size_t boff = ((size_t)b * NN + n0) * CC;
    float acc[4][4][4] = {};
    mma_mainloop<8>(w_hi + (size_t)m0 * CC, w_lo + (size_t)m0 * CC, CC,
                    xt_hi + boff, xt_lo + boff, CC,
                    smemU32, t, wid, lane, acc);

    const int rbase = m0 + (wid >> 2) * 64 + (lane >> 2);
    const int cbase = n0 + (wid & 3) * 32 + (lane & 3) * 2;
#pragma unroll
    for (int mi = 0; mi < 4; mi++) {
        const int ch0 = rbase + mi * 16;
        const float bi0 = bias[ch0], bi1 = bias[ch0 + 8];
#pragma unroll
        for (int ni = 0; ni < 4; ni++) {
            const int cn = cbase + ni * 8;
            const size_t a0 = ((size_t)b * CC + ch0) * NN + cn;
            split_store2(acc[mi][ni][0] + bi0, acc[mi][ni][1] + bi0, Vhi + a0, Vlo + a0);
            const size_t a1 = ((size_t)b * CC + ch0 + 8) * NN + cn;
            split_store2(acc[mi][ni][2] + bi1, acc[mi][ni][3] + bi1, Vhi + a1, Vlo + a1);
        }
    }
}

// ============================================================================
// Energy: E[b][i][j] = sum_d q[i][d] k[j][d]
// ============================================================================
__global__ void __launch_bounds__(256, 1)
mma_energy(const __nv_bfloat16* __restrict__ qhi, const __nv_bfloat16* __restrict__ qlo,
           const __nv_bfloat16* __restrict__ khi, const __nv_bfloat16* __restrict__ klo,
           float* __restrict__ E)
{
    extern __shared__ char smem[];
    const uint32_t smemU32 = smem_to_u32(smem);
    const int t = threadIdx.x, wid = t >> 5, lane = t & 31;
    const int b = blockIdx.z;
    const int i0 = blockIdx.y * 128, j0 = blockIdx.x * 128;

    const size_t aoff = ((size_t)b * NN + i0) * DD;
    const size_t boff = ((size_t)b * NN + j0) * DD;

    float acc[4][4][4] = {};
    mma_mainloop<2>(qhi + aoff, qlo + aoff, DD, khi + boff, klo + boff, DD,
                    smemU32, t, wid, lane, acc);

    float* Eb = E + (size_t)b * NN * NN;
    const int rbase = i0 + (wid >> 2) * 64 + (lane >> 2);
    const int cbase = j0 + (wid & 3) * 32 + (lane & 3) * 2;
#pragma unroll
    for (int mi = 0; mi < 4; mi++)
#pragma unroll
        for (int ni = 0; ni < 4; ni++) {
            const int r = rbase + mi * 16;
            const int cjj = cbase + ni * 8;
            *(float2*)&Eb[(size_t)r * NN + cjj]       = make_float2(acc[mi][ni][0], acc[mi][ni][1]);
            *(float2*)&Eb[(size_t)(r + 8) * NN + cjj] = make_float2(acc[mi][ni][2], acc[mi][ni][3]);
        }
}

// ============================================================================
// Out: out[b][c][i] = g * (sum_j v[c][j] p[i][j]) * inv[i] + x[c][i]
// ============================================================================
__global__ void __launch_bounds__(256, 1)
mma_out(const __nv_bfloat16* __restrict__ vhi, const __nv_bfloat16* __restrict__ vlo,
        const __nv_bfloat16* __restrict__ phi, const __nv_bfloat16* __restrict__ plo,
        const float* __restrict__ X, const float* __restrict__ gamma,
        const float* __restrict__ invs, float* __restrict__ Out)
{
    extern __shared__ char smem[];
    const uint32_t smemU32 = smem_to_u32(smem);
    const int t = threadIdx.x, wid = t >> 5, lane = t & 31;
    const int b = blockIdx.z;
    const int c0 = blockIdx.x * 128, i0 = blockIdx.y * 128;

    const size_t aoff = ((size_t)b * CC + c0) * NN;
    const size_t boff = ((size_t)b * NN + i0) * NN;

    float acc[4][4][4] = {};
    mma_mainloop<64>(vhi + aoff, vlo + aoff, NN, phi + boff, plo + boff, NN,
                     smemU32, t, wid, lane, acc);

    const float g = __ldg(gamma);
    const int rbase = c0 + (wid >> 2) * 64 + (lane >> 2);
    const int cbase = i0 + (wid & 3) * 32 + (lane & 3) * 2;
    const float* ivb = invs + b * NN;
#pragma unroll
    for (int mi = 0; mi < 4; mi++)
#pragma unroll
        for (int ni = 0; ni < 4; ni++) {
            const int ch = rbase + mi * 16;
            const int ci = cbase + ni * 8;
            const float2 iv = *(const float2*)&ivb[ci];
            {
                const size_t idx = ((size_t)b * CC + ch) * NN + ci;
                const float2 xv = *(const float2*)&X[idx];
                float2 o;
                o.x = g * acc[mi][ni][0] * iv.x + xv.x;
                o.y = g * acc[mi][ni][1] * iv.y + xv.y;
                *(float2*)&Out[idx] = o;
            }
            {
                const size_t idx = ((size_t)b * CC + ch + 8) * NN + ci;
                const float2 xv = *(const float2*)&X[idx];
                float2 o;
                o.x = g * acc[mi][ni][2] * iv.x + xv.x;
                o.y = g * acc[mi][ni][3] * iv.y + xv.y;
                *(float2*)&Out[idx] = o;
            }
        }
}

// ============================================================================
// Softmax: fp32 energy row -> unnormalized exp bf16 hi/lo + 1/rowsum
// ============================================================================
__global__ void __launch_bounds__(256)
softmax_rows(const float* __restrict__ E,
             __nv_bfloat16* __restrict__ Phi, __nv_bfloat16* __restrict__ Plo,
             float* __restrict__ invs)
{
    __shared__ float red[8];
    const float4* E4 = (const float4*)E;
    const size_t base4 = (size_t)blockIdx.x * (NN / 4);
    const int tid = threadIdx.x;
    const int lane = tid & 31, wid = tid >> 5;

    float4 v[4];
#pragma unroll
    for (int u = 0; u < 4; u++) v[u] = E4[base4 + u * 256 + tid];

    float m = -1e30f;
#pragma unroll
    for (int u = 0; u < 4; u++)
        m = fmaxf(m, fmaxf(fmaxf(v[u].x, v[u].y), fmaxf(v[u].z, v[u].w)));
#pragma unroll
    for (int off = 16; off > 0; off >>= 1)
        m = fmaxf(m, __shfl_xor_sync(0xffffffffu, m, off));
    if (lane == 0) red[wid] = m;
    __syncthreads();
    m = red[0];
#pragma unroll
    for (int w = 1; w < 8; w++) m = fmaxf(m, red[w]);
    __syncthreads();

    float s = 0.f;
#pragma unroll
    for (int u = 0; u < 4; u++) {
        v[u].x = __expf(v[u].x - m); v[u].y = __expf(v[u].y - m);
        v[u].z = __expf(v[u].z - m); v[u].w = __expf(v[u].w - m);
        s += v[u].x + v[u].y + v[u].z + v[u].w;
    }
#pragma unroll
    for (int off = 16; off > 0; off >>= 1)
        s += __shfl_xor_sync(0xffffffffu, s, off);
    if (lane == 0) red[wid] = s;
    __syncthreads();
    s = red[0];
#pragma unroll
    for (int w = 1; w < 8; w++) s += red[w];

#pragma unroll
    for (int u = 0; u < 4; u++) {
        const size_t el = base4 * 4 + (u * 256 + tid) * 4;
        float f[4] = { v[u].x, v[u].y, v[u].z, v[u].w };
        __nv_bfloat16 h[4], l[4];
        split4(f, h, l);
        *(uint2*)&Phi[el] = *(uint2*)h;
        *(uint2*)&Plo[el] = *(uint2*)l;
    }
    if (tid == 0) invs[blockIdx.x] = 1.0f / s;
}

// ============================================================================

extern "C" void kernel_launch(void* const* d_in, const int* in_sizes, int n_in,
                              void* d_out, int out_size)
{
    const float* x     = (const float*)d_in[0];
    const float* dep   = (const float*)d_in[1];
    const float* wq    = (const float*)d_in[2];
    const float* bq    = (const float*)d_in[3];
    const float* wqd   = (const float*)d_in[4];
    const float* bqd   = (const float*)d_in[5];
    const float* wk    = (const float*)d_in[6];
    const float* bk    = (const float*)d_in[7];
    const float* wkd   = (const float*)d_in[8];
    const float* bkd   = (const float*)d_in[9];
    const float* wv    = (const float*)d_in[10];
    const float* bv    = (const float*)d_in[11];
    const float* gamma = (const float*)d_in[12];
    float* out = (float*)d_out;

    __nv_bfloat16 *xt_hi, *xt_lo, *dt_hi, *dt_lo;
    __nv_bfloat16 *wqk_hi, *wqk_lo, *wqkd_hi, *wqkd_lo, *wv_hi, *wv_lo;
    __nv_bfloat16 *qhi, *qlo, *khi, *klo, *vhi, *vlo, *phi, *plo;
    float *e, *s;
    cudaGetSymbolAddress((void**)&xt_hi, g_xt_hi);
    cudaGetSymbolAddress((void**)&xt_lo, g_xt_lo);
    cudaGetSymbolAddress((void**)&dt_hi, g_dt_hi);
    cudaGetSymbolAddress((void**)&dt_lo, g_dt_lo);
    cudaGetSymbolAddress((void**)&wqk_hi, g_wqk_hi);
    cudaGetSymbolAddress((void**)&wqk_lo, g_wqk_lo);
    cudaGetSymbolAddress((void**)&wqkd_hi, g_wqkd_hi);
    cudaGetSymbolAddress((void**)&wqkd_lo, g_wqkd_lo);
    cudaGetSymbolAddress((void**)&wv_hi, g_wv_hi);
    cudaGetSymbolAddress((void**)&wv_lo, g_wv_lo);
    cudaGetSymbolAddress((void**)&qhi, g_qhi);
    cudaGetSymbolAddress((void**)&qlo, g_qlo);
    cudaGetSymbolAddress((void**)&khi, g_khi);
    cudaGetSymbolAddress((void**)&klo, g_klo);
    cudaGetSymbolAddress((void**)&vhi, g_vhi);
    cudaGetSymbolAddress((void**)&vlo, g_vlo);
    cudaGetSymbolAddress((void**)&phi, g_phi);
    cudaGetSymbolAddress((void**)&plo, g_plo);
    cudaGetSymbolAddress((void**)&e, g_e);
    cudaGetSymbolAddress((void**)&s, g_s);

    cudaFuncSetAttribute(mma_proj_qk, cudaFuncAttributeMaxDynamicSharedMemorySize, MMA_SMEM_BYTES);
    cudaFuncSetAttribute(mma_proj_v,  cudaFuncAttributeMaxDynamicSharedMemorySize, MMA_SMEM_BYTES);
    cudaFuncSetAttribute(mma_energy,  cudaFuncAttributeMaxDynamicSharedMemorySize, MMA_SMEM_BYTES);
    cudaFuncSetAttribute(mma_out,     cudaFuncAttributeMaxDynamicSharedMemorySize, MMA_SMEM_BYTES);

    // input prep: transpose+split x/dep, split weights
    dim3 tthr(32, 8);
    transpose_split<<<dim3(NN / 32, CC / 32, BB), tthr>>>(x,   xt_hi, xt_lo);
    transpose_split<<<dim3(NN / 32, CC / 32, BB), tthr>>>(dep, dt_hi, dt_lo);
    weight_split<<<(768 * 512 + 255) / 256, 256>>>(wq, wk, wqd, wkd, wv,
                                                   wqk_hi, wqk_lo, wqkd_hi, wqkd_lo,
                                                   wv_hi, wv_lo);

    // projections (all tensor-core)
    mma_proj_qk<<<dim3(NN / 128, 1, BB), 256, MMA_SMEM_BYTES>>>(
        xt_hi, xt_lo, wqk_hi, wqk_lo, bq, bk, qhi, qlo, khi, klo, 0);
    mma_proj_qk<<<dim3(NN / 128, 1, BB), 256, MMA_SMEM_BYTES>>>(
        dt_hi, dt_lo, wqkd_hi, wqkd_lo, bqd, bkd, qhi, qlo, khi, klo, CQ);
    mma_proj_v<<<dim3(NN / 128, CC / 128, BB), 256, MMA_SMEM_BYTES>>>(
        wv_hi, wv_lo, xt_hi, xt_lo, bv, vhi, vlo);

    // energy
    mma_energy<<<dim3(NN / 128, NN / 128, BB), 256, MMA_SMEM_BYTES>>>(qhi, qlo, khi, klo, e);

    // softmax -> exp hi/lo + 1/rowsum
    softmax_rows<<<BB * NN, 256>>>(e, phi, plo, s);

    // out
    mma_out<<<dim3(CC / 128, NN / 128, BB), 256, MMA_SMEM_BYTES>>>(vhi, vlo, phi, plo, x, gamma, s, out);
}

// round 8
// speedup vs baseline: 1.5137x; 1.5137x over previous
#include <cuda_runtime.h>
#include <cuda_bf16.h>
#include <cstdint>

#define BB 4
#define CC 512
#define CQ 64
#define DD 128   // 2*CQ
#define NN 4096  // H*W

// ---------------- scratch (device globals; no allocations allowed) ----------
__device__ __align__(256) __nv_bfloat16 g_xt_hi[BB * NN * CC];  // x^T [b][n][c]
__device__ __align__(256) __nv_bfloat16 g_xt_lo[BB * NN * CC];
__device__ __align__(256) __nv_bfloat16 g_dt_hi[BB * NN * CC];  // dep^T
__device__ __align__(256) __nv_bfloat16 g_dt_lo[BB * NN * CC];
__device__ __align__(256) __nv_bfloat16 g_wqk_hi[DD * CC];      // wq rows 0-63, wk rows 64-127
__device__ __align__(256) __nv_bfloat16 g_wqk_lo[DD * CC];
__device__ __align__(256) __nv_bfloat16 g_wqkd_hi[DD * CC];
__device__ __align__(256) __nv_bfloat16 g_wqkd_lo[DD * CC];
__device__ __align__(256) __nv_bfloat16 g_wv_hi[CC * CC];
__device__ __align__(256) __nv_bfloat16 g_wv_lo[CC * CC];
__device__ __align__(256) __nv_bfloat16 g_qhi[BB * NN * DD];    // [b][i][d]
__device__ __align__(256) __nv_bfloat16 g_qlo[BB * NN * DD];
__device__ __align__(256) __nv_bfloat16 g_khi[BB * NN * DD];
__device__ __align__(256) __nv_bfloat16 g_klo[BB * NN * DD];
__device__ __align__(256) __nv_bfloat16 g_vhi[BB * CC * NN];    // [b][c][n]
__device__ __align__(256) __nv_bfloat16 g_vlo[BB * CC * NN];
__device__ __align__(256) float g_e[(size_t)BB * NN * NN];
__device__ __align__(256) __nv_bfloat16 g_phi[(size_t)BB * NN * NN];
__device__ __align__(256) __nv_bfloat16 g_plo[(size_t)BB * NN * NN];
__device__ __align__(256) float g_s[BB * NN];

// ---------------- low-level helpers -----------------------------------------
__device__ __forceinline__ uint32_t smem_to_u32(const void* p) {
    uint32_t a;
    asm("{ .reg .u64 t; cvta.to.shared.u64 t, %1; cvt.u32.u64 %0, t; }" : "=r"(a) : "l"(p));
    return a;
}
#define SWZ(off) ((off) ^ (((off) >> 3) & 0x70))

__device__ __forceinline__ void cp16(uint32_t dst, const void* src) {
    asm volatile("cp.async.cg.shared.global [%0], [%1], 16;" :: "r"(dst), "l"(src));
}
__device__ __forceinline__ void cp_commit() {
    asm volatile("cp.async.commit_group;" ::: "memory");
}
__device__ __forceinline__ void ldsm4(uint32_t r[4], uint32_t addr) {
    asm volatile("ldmatrix.sync.aligned.m8n8.x4.shared.b16 {%0,%1,%2,%3}, [%4];"
                 : "=r"(r[0]), "=r"(r[1]), "=r"(r[2]), "=r"(r[3]) : "r"(addr));
}
__device__ __forceinline__ void mma_bf16(float acc[4], const uint32_t a[4],
                                         uint32_t b0, uint32_t b1) {
    asm volatile("mma.sync.aligned.m16n8k16.row.col.f32.bf16.bf16.f32 "
                 "{%0,%1,%2,%3}, {%4,%5,%6,%7}, {%8,%9}, {%0,%1,%2,%3};"
                 : "+f"(acc[0]), "+f"(acc[1]), "+f"(acc[2]), "+f"(acc[3])
                 : "r"(a[0]), "r"(a[1]), "r"(a[2]), "r"(a[3]), "r"(b0), "r"(b1));
}
__device__ __forceinline__ void split4(const float f[4], __nv_bfloat16 h[4], __nv_bfloat16 l[4])
{
#pragma unroll
    for (int i = 0; i < 4; i++) {
        h[i] = __float2bfloat16(f[i]);
        l[i] = __float2bfloat16(f[i] - __bfloat162float(h[i]));
    }
}
__device__ __forceinline__ void split_store2(float v0, float v1,
                                             __nv_bfloat16* dh, __nv_bfloat16* dl)
{
    __nv_bfloat16 h0 = __float2bfloat16(v0), h1 = __float2bfloat16(v1);
    __nv_bfloat16 l0 = __float2bfloat16(v0 - __bfloat162float(h0));
    __nv_bfloat16 l1 = __float2bfloat16(v1 - __bfloat162float(h1));
    __nv_bfloat162 H; H.x = h0; H.y = h1;
    __nv_bfloat162 L; L.x = l0; L.y = l1;
    *(__nv_bfloat162*)dh = H;
    *(__nv_bfloat162*)dl = L;
}

// ---------------- split-bf16 MMA machinery (R6-proven 2-stage) ---------------
// Stage layout (64KB/stage, 2 stages = 128KB):
//   +0      A_hi 128x64 bf16 (128B swizzled rows)
//   +16384  A_lo
//   +32768  B_hi
//   +49152  B_lo
#define STG 65536
#define MMA_SMEM_BYTES (2 * STG)

__device__ __forceinline__ void stage_load(
    const __nv_bfloat16* __restrict__ Ahi, const __nv_bfloat16* __restrict__ Alo,
    size_t aStr,
    const __nv_bfloat16* __restrict__ Bhi, const __nv_bfloat16* __restrict__ Blo,
    size_t bStr, int kt, uint32_t stageU32, int t)
{
#pragma unroll
    for (int i = 0; i < 4; i++) {
        const int id = t + i * 256;
        const int row = id >> 3, c16 = id & 7;
        const uint32_t doff = SWZ((uint32_t)(row * 128 + c16 * 16));
        const size_t so = (size_t)row * aStr + kt + c16 * 8;
        cp16(stageU32 + doff,          Ahi + so);
        cp16(stageU32 + 16384 + doff,  Alo + so);
        const size_t sb = (size_t)row * bStr + kt + c16 * 8;
        cp16(stageU32 + 32768 + doff,  Bhi + sb);
        cp16(stageU32 + 49152 + doff,  Blo + sb);
    }
}

__device__ __forceinline__ void stage_compute(uint32_t stageU32, int wid, int lane,
                                              float acc[4][4][4])
{
    const int warp_row = wid >> 2;
    const int warp_col = wid & 3;
    const int lrow = lane & 15;
    const int chalf = (lane >= 16) ? 16 : 0;

#pragma unroll
    for (int ks = 0; ks < 4; ks++) {
        const uint32_t bcol = ks * 32 + chalf;
        uint32_t ahi[4][4], alo[4][4];
#pragma unroll
        for (int mi = 0; mi < 4; mi++) {
            const uint32_t off = SWZ((uint32_t)((warp_row * 64 + mi * 16 + lrow) * 128 + bcol));
            ldsm4(ahi[mi], stageU32 + off);
            ldsm4(alo[mi], stageU32 + 16384 + off);
        }
        uint32_t bhi[2][4], blo[2][4];
#pragma unroll
        for (int nh = 0; nh < 2; nh++) {
            const uint32_t off = SWZ((uint32_t)((warp_col * 32 + nh * 16 + lrow) * 128 + bcol));
            ldsm4(bhi[nh], stageU32 + 32768 + off);
            ldsm4(blo[nh], stageU32 + 49152 + off);
        }
#pragma unroll
        for (int mi = 0; mi < 4; mi++)
#pragma unroll
            for (int ni = 0; ni < 4; ni++) {
                const int nh = ni >> 1, s = ni & 1;
                mma_bf16(acc[mi][ni], ahi[mi], bhi[nh][s], bhi[nh][s + 2]);
                mma_bf16(acc[mi][ni], alo[mi], bhi[nh][s], bhi[nh][s + 2]);
                mma_bf16(acc[mi][ni], ahi[mi], blo[nh][s], blo[nh][s + 2]);
            }
    }
}

// R6-exact 2-stage pipelined K loop.
template <int KCHUNKS>
__device__ __forceinline__ void mma_mainloop(
    const __nv_bfloat16* Ahi, const __nv_bfloat16* Alo, size_t aStr,
    const __nv_bfloat16* Bhi, const __nv_bfloat16* Blo, size_t bStr,
    uint32_t smemU32, int t, int wid, int lane, float acc[4][4][4])
{
    stage_load(Ahi, Alo, aStr, Bhi, Blo, bStr, 0, smemU32, t);
    cp_commit();
    for (int c = 0; c < KCHUNKS; c++) {
        const bool more = (c + 1) < KCHUNKS;
        if (more) {
            stage_load(Ahi, Alo, aStr, Bhi, Blo, bStr, (c + 1) * 64,
                       smemU32 + ((c + 1) & 1) * STG, t);
            cp_commit();
            asm volatile("cp.async.wait_group 1;" ::: "memory");
        } else {
            asm volatile("cp.async.wait_group 0;" ::: "memory");
        }
        __syncthreads();
        stage_compute(smemU32 + (c & 1) * STG, wid, lane, acc);
        __syncthreads();
    }
}

// ============================================================================
// transpose + split: src [b][C][N] fp32 -> dst [b][N][C] bf16 hi/lo
// ============================================================================
__global__ void __launch_bounds__(256)
transpose_split(const float* __restrict__ src,
                __nv_bfloat16* __restrict__ dhi, __nv_bfloat16* __restrict__ dlo)
{
    __shared__ float tile[32][33];
    const int b = blockIdx.z;
    const int n0 = blockIdx.x * 32, c0 = blockIdx.y * 32;
    const int tx = threadIdx.x, ty = threadIdx.y;   // (32, 8)
    const float* S = src + (size_t)b * CC * NN;
#pragma unroll
    for (int i = 0; i < 4; i++)
        tile[ty * 4 + i][tx] = S[(size_t)(c0 + ty * 4 + i) * NN + n0 + tx];
    __syncthreads();
    __nv_bfloat16* H = dhi + (size_t)b * NN * CC;
    __nv_bfloat16* L = dlo + (size_t)b * NN * CC;
#pragma unroll
    for (int i = 0; i < 4; i++) {
        const float f = tile[tx][ty * 4 + i];
        const __nv_bfloat16 h = __float2bfloat16(f);
        const __nv_bfloat16 l = __float2bfloat16(f - __bfloat162float(h));
        const size_t idx = (size_t)(n0 + ty * 4 + i) * CC + c0 + tx;
        H[idx] = h;
        L[idx] = l;
    }
}

// ============================================================================
// weight split: wv (512 rows) + wq/wk -> wqk (128 rows) + wqd/wkd -> wqkd
// ============================================================================
__global__ void __launch_bounds__(256)
weight_split(const float* __restrict__ wq, const float* __restrict__ wk,
             const float* __restrict__ wqd, const float* __restrict__ wkd,
             const float* __restrict__ wv,
             __nv_bfloat16* __restrict__ wqk_hi, __nv_bfloat16* __restrict__ wqk_lo,
             __nv_bfloat16* __restrict__ wqkd_hi, __nv_bfloat16* __restrict__ wqkd_lo,
             __nv_bfloat16* __restrict__ wv_hi, __nv_bfloat16* __restrict__ wv_lo)
{
    const int idx = blockIdx.x * 256 + threadIdx.x;
    if (idx >= 768 * 512) return;
    const int row = idx >> 9, col = idx & 511;
    const float* src;
    __nv_bfloat16 *dh, *dl;
    int drow;
    if (row < 512)      { src = wv  + (size_t)row * 512;         dh = wv_hi;   dl = wv_lo;   drow = row; }
    else if (row < 576) { src = wq  + (size_t)(row - 512) * 512; dh = wqk_hi;  dl = wqk_lo;  drow = row - 512; }
    else if (row < 640) { src = wk  + (size_t)(row - 576) * 512; dh = wqk_hi;  dl = wqk_lo;  drow = row - 576 + 64; }
    else if (row < 704) { src = wqd + (size_t)(row - 640) * 512; dh = wqkd_hi; dl = wqkd_lo; drow = row - 640; }
    else                { src = wkd + (size_t)(row - 704) * 512; dh = wqkd_hi; dl = wqkd_lo; drow = row - 704 + 64; }
    const float f = src[col];
    const __nv_bfloat16 h = __float2bfloat16(f);
    dh[(size_t)drow * 512 + col] = h;
    dl[(size_t)drow * 512 + col] = __float2bfloat16(f - __bfloat162float(h));
}

// ============================================================================
// proj qk: [n][d] tile = xt[n][c] . wqk[d][c],  d 0-63 -> q(+d_off), 64-127 -> k
// ============================================================================
__global__ void __launch_bounds__(256, 1)
mma_proj_qk(const __nv_bfloat16* __restrict__ xt_hi, const __nv_bfloat16* __restrict__ xt_lo,
            const __nv_bfloat16* __restrict__ w_hi,  const __nv_bfloat16* __restrict__ w_lo,
            const float* __restrict__ bias_q, const float* __restrict__ bias_k,
            __nv_bfloat16* __restrict__ Qhi, __nv_bfloat16* __restrict__ Qlo,
            __nv_bfloat16* __restrict__ Khi, __nv_bfloat16* __restrict__ Klo,
            int d_off)
{
    extern __shared__ char smem[];
    const uint32_t smemU32 = smem_to_u32(smem);
    const int t = threadIdx.x, wid = t >> 5, lane = t & 31;
    const int b = blockIdx.z;
    const int i0 = blockIdx.x * 128;

    const size_t aoff = ((size_t)b * NN + i0) * CC;
    float acc[4][4][4] = {};
    mma_mainloop<8>(xt_hi + aoff, xt_lo + aoff, CC, w_hi, w_lo, CC,
                    smemU32, t, wid, lane, acc);

    const int warp_col = wid & 3;
    const bool isK = warp_col >= 2;
    const float* bias = isK ? bias_k : bias_q;
    __nv_bfloat16* DH = isK ? Khi : Qhi;
    __nv_bfloat16* DL = isK ? Klo : Qlo;
    const int csub = isK ? 64 : 0;

    const int rbase = i0 + (wid >> 2) * 64 + (lane >> 2);
    const int cbase = warp_col * 32 + (lane & 3) * 2;
#pragma unroll
    for (int mi = 0; mi < 4; mi++)
#pragma unroll
        for (int ni = 0; ni < 4; ni++) {
            const int col = cbase + ni * 8 - csub;   // 0..63
            const float2 bi = *(const float2*)&bias[col];
            const int r0 = rbase + mi * 16;
            const size_t a0 = ((size_t)b * NN + r0) * DD + d_off + col;
            split_store2(acc[mi][ni][0] + bi.x, acc[mi][ni][1] + bi.y, DH + a0, DL + a0);
            const size_t a1 = ((size_t)b * NN + r0 + 8) * DD + d_off + col;
            split_store2(acc[mi][ni][2] + bi.x, acc[mi][ni][3] + bi.y, DH + a1, DL + a1);
        }
}

// ============================================================================
// proj v: [c][n] tile = wv[c][k] . xt[n][k]
// ============================================================================
__global__ void __launch_bounds__(256, 1)
mma_proj_v(const __nv_bfloat16* __restrict__ w_hi, const __nv_bfloat16* __restrict__ w_lo,
           const __nv_bfloat16* __restrict__ xt_hi, const __nv_bfloat16* __restrict__ xt_lo,
           const float* __restrict__ bias,
           __nv_bfloat16* __restrict__ Vhi, __nv_bfloat16* __restrict__ Vlo)
{
    extern __shared__ char smem[];
    const uint32_t smemU32 = smem_to_u32(smem);
    const int t = threadIdx.x, wid = t >> 5, lane = t & 31;
    const int b = blockIdx.z;
    const int n0 = blockIdx.x * 128, m0 = blockIdx.y * 128;

    const size_t boff = ((size_t)b * NN + n0) * CC;
    float acc[4][4][4] = {};
    mma_mainloop<8>(w_hi + (size_t)m0 * CC, w_lo + (size_t)m0 * CC, CC,
                    xt_hi + boff, xt_lo + boff, CC,
                    smemU32, t, wid, lane, acc);

    const int rbase = m0 + (wid >> 2) * 64 + (lane >> 2);
    const int cbase = n0 + (wid & 3) * 32 + (lane & 3) * 2;
#pragma unroll
    for (int mi = 0; mi < 4; mi++) {
        const int ch0 = rbase + mi * 16;
        const float bi0 = bias[ch0], bi1 = bias[ch0 + 8];
#pragma unroll
        for (int ni = 0; ni < 4; ni++) {
            const int cn = cbase + ni * 8;
            const size_t a0 = ((size_t)b * CC + ch0) * NN + cn;
            split_store2(acc[mi][ni][0] + bi0, acc[mi][ni][1] + bi0, Vhi + a0, Vlo + a0);
            const size_t a1 = ((size_t)b * CC + ch0 + 8) * NN + cn;
            split_store2(acc[mi][ni][2] + bi1, acc[mi][ni][3] + bi1, Vhi + a1, Vlo + a1);
        }
    }
}

// ============================================================================
// Energy: E[b][i][j] = sum_d q[i][d] k[j][d]
// ============================================================================
__global__ void __launch_bounds__(256, 1)
mma_energy(const __nv_bfloat16* __restrict__ qhi, const __nv_bfloat16* __restrict__ qlo,
           const __nv_bfloat16* __restrict__ khi, const __nv_bfloat16* __restrict__ klo,
           float* __restrict__ E)
{
    extern __shared__ char smem[];
    const uint32_t smemU32 = smem_to_u32(smem);
    const int t = threadIdx.x, wid = t >> 5, lane = t & 31;
    const int b = blockIdx.z;
    const int i0 = blockIdx.y * 128, j0 = blockIdx.x * 128;

    const size_t aoff = ((size_t)b * NN + i0) * DD;
    const size_t boff = ((size_t)b * NN + j0) * DD;

    float acc[4][4][4] = {};
    mma_mainloop<2>(qhi + aoff, qlo + aoff, DD, khi + boff, klo + boff, DD,
                    smemU32, t, wid, lane, acc);

    float* Eb = E + (size_t)b * NN * NN;
    const int rbase = i0 + (wid >> 2) * 64 + (lane >> 2);
    const int cbase = j0 + (wid & 3) * 32 + (lane & 3) * 2;
#pragma unroll
    for (int mi = 0; mi < 4; mi++)
#pragma unroll
        for (int ni = 0; ni < 4; ni++) {
            const int r = rbase + mi * 16;
            const int cjj = cbase + ni * 8;
            *(float2*)&Eb[(size_t)r * NN + cjj]       = make_float2(acc[mi][ni][0], acc[mi][ni][1]);
            *(float2*)&Eb[(size_t)(r + 8) * NN + cjj] = make_float2(acc[mi][ni][2], acc[mi][ni][3]);
        }
}

// ============================================================================
// Out: out[b][c][i] = g * (sum_j v[c][j] p[i][j]) * inv[i] + x[c][i]
// ============================================================================
__global__ void __launch_bounds__(256, 1)
mma_out(const __nv_bfloat16* __restrict__ vhi, const __nv_bfloat16* __restrict__ vlo,
        const __nv_bfloat16* __restrict__ phi, const __nv_bfloat16* __restrict__ plo,
        const float* __restrict__ X, const float* __restrict__ gamma,
        const float* __restrict__ invs, float* __restrict__ Out)
{
    extern __shared__ char smem[];
    const uint32_t smemU32 = smem_to_u32(smem);
    const int t = threadIdx.x, wid = t >> 5, lane = t & 31;
    const int b = blockIdx.z;
    const int c0 = blockIdx.x * 128, i0 = blockIdx.y * 128;

    const size_t aoff = ((size_t)b * CC + c0) * NN;
    const size_t boff = ((size_t)b * NN + i0) * NN;

    float acc[4][4][4] = {};
    mma_mainloop<64>(vhi + aoff, vlo + aoff, NN, phi + boff, plo + boff, NN,
                     smemU32, t, wid, lane, acc);

    const float g = __ldg(gamma);
    const int rbase = c0 + (wid >> 2) * 64 + (lane >> 2);
    const int cbase = i0 + (wid & 3) * 32 + (lane & 3) * 2;
    const float* ivb = invs + b * NN;
#pragma unroll
    for (int mi = 0; mi < 4; mi++)
#pragma unroll
        for (int ni = 0; ni < 4; ni++) {
            const int ch = rbase + mi * 16;
            const int ci = cbase + ni * 8;
            const float2 iv = *(const float2*)&ivb[ci];
            {
                const size_t idx = ((size_t)b * CC + ch) * NN + ci;
                const float2 xv = *(const float2*)&X[idx];
                float2 o;
                o.x = g * acc[mi][ni][0] * iv.x + xv.x;
                o.y = g * acc[mi][ni][1] * iv.y + xv.y;
                *(float2*)&Out[idx] = o;
            }
            {
                const size_t idx = ((size_t)b * CC + ch + 8) * NN + ci;
                const float2 xv = *(const float2*)&X[idx];
                float2 o;
                o.x = g * acc[mi][ni][2] * iv.x + xv.x;
                o.y = g * acc[mi][ni][3] * iv.y + xv.y;
                *(float2*)&Out[idx] = o;
            }
        }
}

// ============================================================================
// Softmax: fp32 energy row -> unnormalized exp bf16 hi/lo + 1/rowsum
// ============================================================================
__global__ void __launch_bounds__(256)
softmax_rows(const float* __restrict__ E,
             __nv_bfloat16* __restrict__ Phi, __nv_bfloat16* __restrict__ Plo,
             float* __restrict__ invs)
{
    __shared__ float red[8];
    const float4* E4 = (const float4*)E;
    const size_t base4 = (size_t)blockIdx.x * (NN / 4);
    const int tid = threadIdx.x;
    const int lane = tid & 31, wid = tid >> 5;

    float4 v[4];
#pragma unroll
    for (int u = 0; u < 4; u++) v[u] = E4[base4 + u * 256 + tid];

    float m = -1e30f;
#pragma unroll
    for (int u = 0; u < 4; u++)
        m = fmaxf(m, fmaxf(fmaxf(v[u].x, v[u].y), fmaxf(v[u].z, v[u].w)));
#pragma unroll
    for (int off = 16; off > 0; off >>= 1)
        m = fmaxf(m, __shfl_xor_sync(0xffffffffu, m, off));
    if (lane == 0) red[wid] = m;
    __syncthreads();
    m = red[0];
#pragma unroll
    for (int w = 1; w < 8; w++) m = fmaxf(m, red[w]);
    __syncthreads();

    float s = 0.f;
#pragma unroll
    for (int u = 0; u < 4; u++) {
        v[u].x = __expf(v[u].x - m); v[u].y = __expf(v[u].y - m);
        v[u].z = __expf(v[u].z - m); v[u].w = __expf(v[u].w - m);
        s += v[u].x + v[u].y + v[u].z + v[u].w;
    }
#pragma unroll
    for (int off = 16; off > 0; off >>= 1)
        s += __shfl_xor_sync(0xffffffffu, s, off);
    if (lane == 0) red[wid] = s;
    __syncthreads();
    s = red[0];
#pragma unroll
    for (int w = 1; w < 8; w++) s += red[w];

#pragma unroll
    for (int u = 0; u < 4; u++) {
        const size_t el = base4 * 4 + (u * 256 + tid) * 4;
        float f[4] = { v[u].x, v[u].y, v[u].z, v[u].w };
        __nv_bfloat16 h[4], l[4];
        split4(f, h, l);
        *(uint2*)&Phi[el] = *(uint2*)h;
        *(uint2*)&Plo[el] = *(uint2*)l;
    }
    if (tid == 0) invs[blockIdx.x] = 1.0f / s;
}

// ============================================================================

extern "C" void kernel_launch(void* const* d_in, const int* in_sizes, int n_in,
                              void* d_out, int out_size)
{
    const float* x     = (const float*)d_in[0];
    const float* dep   = (const float*)d_in[1];
    const float* wq    = (const float*)d_in[2];
    const float* bq    = (const float*)d_in[3];
    const float* wqd   = (const float*)d_in[4];
    const float* bqd   = (const float*)d_in[5];
    const float* wk    = (const float*)d_in[6];
    const float* bk    = (const float*)d_in[7];
    const float* wkd   = (const float*)d_in[8];
    const float* bkd   = (const float*)d_in[9];
    const float* wv    = (const float*)d_in[10];
    const float* bv    = (const float*)d_in[11];
    const float* gamma = (const float*)d_in[12];
    float* out = (float*)d_out;

    __nv_bfloat16 *xt_hi, *xt_lo, *dt_hi, *dt_lo;
    __nv_bfloat16 *wqk_hi, *wqk_lo, *wqkd_hi, *wqkd_lo, *wv_hi, *wv_lo;
    __nv_bfloat16 *qhi, *qlo, *khi, *klo, *vhi, *vlo, *phi, *plo;
    float *e, *s;
    cudaGetSymbolAddress((void**)&xt_hi, g_xt_hi);
    cudaGetSymbolAddress((void**)&xt_lo, g_xt_lo);
    cudaGetSymbolAddress((void**)&dt_hi, g_dt_hi);
    cudaGetSymbolAddress((void**)&dt_lo, g_dt_lo);
    cudaGetSymbolAddress((void**)&wqk_hi, g_wqk_hi);
    cudaGetSymbolAddress((void**)&wqk_lo, g_wqk_lo);
    cudaGetSymbolAddress((void**)&wqkd_hi, g_wqkd_hi);
    cudaGetSymbolAddress((void**)&wqkd_lo, g_wqkd_lo);
    cudaGetSymbolAddress((void**)&wv_hi, g_wv_hi);
    cudaGetSymbolAddress((void**)&wv_lo, g_wv_lo);
    cudaGetSymbolAddress((void**)&qhi, g_qhi);
    cudaGetSymbolAddress((void**)&qlo, g_qlo);
    cudaGetSymbolAddress((void**)&khi, g_khi);
    cudaGetSymbolAddress((void**)&klo, g_klo);
    cudaGetSymbolAddress((void**)&vhi, g_vhi);
    cudaGetSymbolAddress((void**)&vlo, g_vlo);
    cudaGetSymbolAddress((void**)&phi, g_phi);
    cudaGetSymbolAddress((void**)&plo, g_plo);
    cudaGetSymbolAddress((void**)&e, g_e);
    cudaGetSymbolAddress((void**)&s, g_s);

    cudaFuncSetAttribute(mma_proj_qk, cudaFuncAttributeMaxDynamicSharedMemorySize, MMA_SMEM_BYTES);
    cudaFuncSetAttribute(mma_proj_v,  cudaFuncAttributeMaxDynamicSharedMemorySize, MMA_SMEM_BYTES);
    cudaFuncSetAttribute(mma_energy,  cudaFuncAttributeMaxDynamicSharedMemorySize, MMA_SMEM_BYTES);
    cudaFuncSetAttribute(mma_out,     cudaFuncAttributeMaxDynamicSharedMemorySize, MMA_SMEM_BYTES);

    // input prep: transpose+split x/dep, split weights
    dim3 tthr(32, 8);
    transpose_split<<<dim3(NN / 32, CC / 32, BB), tthr>>>(x,   xt_hi, xt_lo);
    transpose_split<<<dim3(NN / 32, CC / 32, BB), tthr>>>(dep, dt_hi, dt_lo);
    weight_split<<<(768 * 512 + 255) / 256, 256>>>(wq, wk, wqd, wkd, wv,
                                                   wqk_hi, wqk_lo, wqkd_hi, wqkd_lo,
                                                   wv_hi, wv_lo);

    // projections (all tensor-core)
    mma_proj_qk<<<dim3(NN / 128, 1, BB), 256, MMA_SMEM_BYTES>>>(
        xt_hi, xt_lo, wqk_hi, wqk_lo, bq, bk, qhi, qlo, khi, klo, 0);
    mma_proj_qk<<<dim3(NN / 128, 1, BB), 256, MMA_SMEM_BYTES>>>(
        dt_hi, dt_lo, wqkd_hi, wqkd_lo, bqd, bkd, qhi, qlo, khi, klo, CQ);
    mma_proj_v<<<dim3(NN / 128, CC / 128, BB), 256, MMA_SMEM_BYTES>>>(
        wv_hi, wv_lo, xt_hi, xt_lo, bv, vhi, vlo);

    // energy
    mma_energy<<<dim3(NN / 128, NN / 128, BB), 256, MMA_SMEM_BYTES>>>(qhi, qlo, khi, klo, e);

    // softmax -> exp hi/lo + 1/rowsum
    softmax_rows<<<BB * NN, 256>>>(e, phi, plo, s);

    // out
    mma_out<<<dim3(CC / 128, NN / 128, BB), 256, MMA_SMEM_BYTES>>>(vhi, vlo, phi, plo, x, gamma, s, out);
}